// round 1
// baseline (speedup 1.0000x reference)
#include <cuda_runtime.h>
#include <math.h>

#define B_   2
#define S_   2048
#define E_   1024
#define H_   16
#define D_   64
#define WIN  3

// Scratch for Q,K,V in [B,H,S,D] layout (device globals: allocation-free).
__device__ float g_q[B_*H_*S_*D_];
__device__ float g_k[B_*H_*S_*D_];
__device__ float g_v[B_*H_*S_*D_];

// ---------------------------------------------------------------------------
// Projection GEMM: dst[b,h,s,d] = X[b,s,:] . W[h*64+d,:] + bias[h*64+d]
// X: [B*S, E] row-major, W: [E, E] row-major (out = X @ W^T + b)
// Tile: 128(M) x 64(N) x 16(K), 256 threads, 8x4 per-thread micro-tile.
// ---------------------------------------------------------------------------
#define PBM 128
#define PBN 64
#define PBK 16

__global__ __launch_bounds__(256) void proj_kernel(
    const float* __restrict__ X,
    const float* __restrict__ W,
    const float* __restrict__ bias,
    float* __restrict__ dst)
{
    __shared__ float As[PBK][PBM];   // As[k][m]
    __shared__ float Bs[PBK][PBN];   // Bs[k][n]

    const int tid = threadIdx.x;
    const int tx  = tid & 15;        // 0..15 -> N
    const int ty  = tid >> 4;        // 0..15 -> M
    const int m0  = blockIdx.y * PBM;
    const int n0  = blockIdx.x * PBN;

    float acc[8][4];
#pragma unroll
    for (int i = 0; i < 8; i++)
#pragma unroll
        for (int j = 0; j < 4; j++) acc[i][j] = 0.f;

    const int r  = tid >> 2;          // 0..63
    const int c4 = (tid & 3) * 4;     // 0,4,8,12

    for (int k0 = 0; k0 < E_; k0 += PBK) {
        // Load A tile (128x16) transposed into As[k][m]
#pragma unroll
        for (int p = 0; p < 2; p++) {
            int row = r + p * 64;
            float4 v = *(const float4*)(X + (size_t)(m0 + row) * E_ + k0 + c4);
            As[c4 + 0][row] = v.x;
            As[c4 + 1][row] = v.y;
            As[c4 + 2][row] = v.z;
            As[c4 + 3][row] = v.w;
        }
        // Load B tile (64x16): W rows = output features
        {
            float4 v = *(const float4*)(W + (size_t)(n0 + r) * E_ + k0 + c4);
            Bs[c4 + 0][r] = v.x;
            Bs[c4 + 1][r] = v.y;
            Bs[c4 + 2][r] = v.z;
            Bs[c4 + 3][r] = v.w;
        }
        __syncthreads();

#pragma unroll
        for (int k = 0; k < PBK; k++) {
            float a[8], bb[4];
            *(float4*)&a[0] = *(const float4*)&As[k][ty * 8];
            *(float4*)&a[4] = *(const float4*)&As[k][ty * 8 + 4];
            *(float4*)&bb[0] = *(const float4*)&Bs[k][tx * 4];
#pragma unroll
            for (int i = 0; i < 8; i++)
#pragma unroll
                for (int j = 0; j < 4; j++)
                    acc[i][j] = fmaf(a[i], bb[j], acc[i][j]);
        }
        __syncthreads();
    }

    // Epilogue: add bias, scatter into [B,H,S,D]
#pragma unroll
    for (int i = 0; i < 8; i++) {
        int m = m0 + ty * 8 + i;
        int b = m >> 11;            // m / S_
        int s = m & (S_ - 1);
#pragma unroll
        for (int j = 0; j < 4; j++) {
            int n = n0 + tx * 4 + j;
            int h = n >> 6;
            int d = n & 63;
            dst[(((size_t)b * H_ + h) * S_ + s) * D_ + d] = acc[i][j] + bias[n];
        }
    }
}

// ---------------------------------------------------------------------------
// Flash attention (fp32) with inverted-band mask.
// Q-tile 128, K-tile 64, 256 threads, 8x4 per-thread micro-tile.
// smem (dynamic, 96KB): qs[d][q] 64x128, ks[d][c] 64x64, vs[c][d] 64x64,
//                       ps[c][q] 64x128
// ---------------------------------------------------------------------------
#define QT 128
#define KT 64

extern __shared__ float sm_attn[];

__global__ __launch_bounds__(256) void attn_kernel(float* __restrict__ out)
{
    float* qs = sm_attn;             // [64][128]
    float* ks = sm_attn + 8192;      // [64][64]
    float* vs = sm_attn + 12288;     // [64][64]
    float* ps = sm_attn + 16384;     // [64][128]

    const int tid = threadIdx.x;
    const int tx  = tid & 15;        // key/out-d group
    const int ty  = tid >> 4;        // query row group
    const int qb  = blockIdx.x;      // 0..15
    const int h   = blockIdx.y;
    const int b   = blockIdx.z;

    const float* Q = g_q + ((size_t)b * H_ + h) * S_ * D_;
    const float* K = g_k + ((size_t)b * H_ + h) * S_ * D_;
    const float* V = g_v + ((size_t)b * H_ + h) * S_ * D_;

    const int q0 = qb * QT;

    // Load Q tile, pre-scaled by 1/sqrt(D), transposed qs[d][q]
    for (int idx = tid; idx < QT * 16; idx += 256) {
        int q = idx >> 4;
        int d4 = (idx & 15) * 4;
        float4 v = *(const float4*)(Q + (size_t)(q0 + q) * D_ + d4);
        qs[(d4 + 0) * QT + q] = v.x * 0.125f;
        qs[(d4 + 1) * QT + q] = v.y * 0.125f;
        qs[(d4 + 2) * QT + q] = v.z * 0.125f;
        qs[(d4 + 3) * QT + q] = v.w * 0.125f;
    }

    float m_i[8], l_i[8], o[8][4];
#pragma unroll
    for (int i = 0; i < 8; i++) {
        m_i[i] = -1e30f;
        l_i[i] = 0.f;
#pragma unroll
        for (int j = 0; j < 4; j++) o[i][j] = 0.f;
    }

    for (int kt = 0; kt < S_; kt += KT) {
        __syncthreads();   // previous iter done reading ks/vs (and Q visible on iter 0)

        // Load K (transposed ks[d][c]) and V (natural vs[c][d])
        for (int idx = tid; idx < KT * 16; idx += 256) {
            int c = idx >> 4;
            int d4 = (idx & 15) * 4;
            float4 kv = *(const float4*)(K + (size_t)(kt + c) * D_ + d4);
            ks[(d4 + 0) * KT + c] = kv.x;
            ks[(d4 + 1) * KT + c] = kv.y;
            ks[(d4 + 2) * KT + c] = kv.z;
            ks[(d4 + 3) * KT + c] = kv.w;
            float4 vv = *(const float4*)(V + (size_t)(kt + c) * D_ + d4);
            *(float4*)&vs[c * KT + d4] = vv;
        }
        __syncthreads();

        // S = (Q/8) @ K^T  -- 8x4 micro-tile per thread
        float s[8][4];
#pragma unroll
        for (int i = 0; i < 8; i++)
#pragma unroll
            for (int j = 0; j < 4; j++) s[i][j] = 0.f;

#pragma unroll 8
        for (int d = 0; d < 64; d++) {
            float a[8], bb[4];
            *(float4*)&a[0] = *(const float4*)&qs[d * QT + ty * 8];
            *(float4*)&a[4] = *(const float4*)&qs[d * QT + ty * 8 + 4];
            *(float4*)&bb[0] = *(const float4*)&ks[d * KT + tx * 4];
#pragma unroll
            for (int i = 0; i < 8; i++)
#pragma unroll
                for (int j = 0; j < 4; j++)
                    s[i][j] = fmaf(a[i], bb[j], s[i][j]);
        }

        // Inverted-band mask: |q-k| <= WIN is masked OUT
#pragma unroll
        for (int i = 0; i < 8; i++) {
            int qg = q0 + ty * 8 + i;
#pragma unroll
            for (int j = 0; j < 4; j++) {
                int kg = kt + tx * 4 + j;
                int dd = qg - kg;
                if (dd <= WIN && dd >= -WIN) s[i][j] = -1e30f;
            }
        }

        // Row max over the tile (16 tx threads own each row group)
        float mx[8];
#pragma unroll
        for (int i = 0; i < 8; i++) {
            mx[i] = fmaxf(fmaxf(s[i][0], s[i][1]), fmaxf(s[i][2], s[i][3]));
#pragma unroll
            for (int off = 8; off >= 1; off >>= 1)
                mx[i] = fmaxf(mx[i], __shfl_xor_sync(0xffffffffu, mx[i], off));
        }

        // Online softmax update
        float sc[8], rs[8];
#pragma unroll
        for (int i = 0; i < 8; i++) {
            float mnew = fmaxf(m_i[i], mx[i]);
            sc[i] = __expf(m_i[i] - mnew);
            m_i[i] = mnew;
            rs[i] = 0.f;
#pragma unroll
            for (int j = 0; j < 4; j++) {
                s[i][j] = __expf(s[i][j] - mnew);
                rs[i] += s[i][j];
            }
        }
#pragma unroll
        for (int i = 0; i < 8; i++) {
#pragma unroll
            for (int off = 8; off >= 1; off >>= 1)
                rs[i] += __shfl_xor_sync(0xffffffffu, rs[i], off);
            l_i[i] = l_i[i] * sc[i] + rs[i];
#pragma unroll
            for (int j = 0; j < 4; j++) o[i][j] *= sc[i];
        }

        // Write P transposed ps[c][q]
#pragma unroll
        for (int i = 0; i < 8; i++)
#pragma unroll
            for (int j = 0; j < 4; j++)
                ps[(tx * 4 + j) * QT + ty * 8 + i] = s[i][j];
        __syncthreads();

        // O += P @ V
#pragma unroll 8
        for (int c = 0; c < 64; c++) {
            float p8[8], v4[4];
            *(float4*)&p8[0] = *(const float4*)&ps[c * QT + ty * 8];
            *(float4*)&p8[4] = *(const float4*)&ps[c * QT + ty * 8 + 4];
            *(float4*)&v4[0] = *(const float4*)&vs[c * KT + tx * 4];
#pragma unroll
            for (int i = 0; i < 8; i++)
#pragma unroll
                for (int j = 0; j < 4; j++)
                    o[i][j] = fmaf(p8[i], v4[j], o[i][j]);
        }
    }

    // Epilogue: out[b, s, h*64 + d] = o / l
#pragma unroll
    for (int i = 0; i < 8; i++) {
        float inv = 1.0f / l_i[i];
        int sg = q0 + ty * 8 + i;
#pragma unroll
        for (int j = 0; j < 4; j++) {
            out[((size_t)b * S_ + sg) * E_ + h * 64 + tx * 4 + j] = o[i][j] * inv;
        }
    }
}

// ---------------------------------------------------------------------------
extern "C" void kernel_launch(void* const* d_in, const int* in_sizes, int n_in,
                              void* d_out, int out_size)
{
    const float* X  = (const float*)d_in[0];
    const float* Wq = (const float*)d_in[1];
    const float* bq = (const float*)d_in[2];
    const float* Wk = (const float*)d_in[3];
    const float* bk = (const float*)d_in[4];
    const float* Wv = (const float*)d_in[5];
    const float* bv = (const float*)d_in[6];
    float* out = (float*)d_out;

    float *dq, *dk, *dv;
    cudaGetSymbolAddress((void**)&dq, g_q);
    cudaGetSymbolAddress((void**)&dk, g_k);
    cudaGetSymbolAddress((void**)&dv, g_v);

    dim3 pgrid(E_ / PBN, (B_ * S_) / PBM);   // (16, 32)
    proj_kernel<<<pgrid, 256>>>(X, Wq, bq, dq);
    proj_kernel<<<pgrid, 256>>>(X, Wk, bk, dk);
    proj_kernel<<<pgrid, 256>>>(X, Wv, bv, dv);

    static int smem_set = 0;
    (void)smem_set;
    cudaFuncSetAttribute(attn_kernel,
                         cudaFuncAttributeMaxDynamicSharedMemorySize,
                         24576 * sizeof(float));

    dim3 agrid(S_ / QT, H_, B_);             // (16, 16, 2)
    attn_kernel<<<agrid, 256, 24576 * sizeof(float)>>>(out);
}

// round 3
// speedup vs baseline: 2.6272x; 2.6272x over previous
#include <cuda_runtime.h>
#include <cuda_bf16.h>
#include <cstdint>

#define B_   2
#define S_   2048
#define E_   1024
#define H_   16
#define D_   64
#define WIN  3
#define MS_  (B_*S_)          // 4096 rows

typedef __nv_bfloat16 bf16;

// ---------------------------------------------------------------------------
// Device-global scratch (allocation-free)
// ---------------------------------------------------------------------------
__device__ bf16 g_xhi[MS_*E_], g_xlo[MS_*E_];
__device__ bf16 g_wqhi[E_*E_], g_wqlo[E_*E_];
__device__ bf16 g_wkhi[E_*E_], g_wklo[E_*E_];
__device__ bf16 g_wvhi[E_*E_], g_wvlo[E_*E_];
__device__ bf16 g_qhi[B_*H_*S_*D_], g_qlo[B_*H_*S_*D_];
__device__ bf16 g_khi[B_*H_*S_*D_], g_klo[B_*H_*S_*D_];
__device__ bf16 g_vhi[B_*H_*S_*D_], g_vlo[B_*H_*S_*D_];

// ---------------------------------------------------------------------------
// Helpers: smem addr, cp.async, ldmatrix, mma (all plain sm_80-level PTX)
// ---------------------------------------------------------------------------
__device__ __forceinline__ uint32_t smem_u32(const void* p) {
    uint32_t a;
    asm("{ .reg .u64 t; cvta.to.shared.u64 t, %1; cvt.u32.u64 %0, t; }"
        : "=r"(a) : "l"(p));
    return a;
}

__device__ __forceinline__ void cp16(uint32_t dst, const void* src) {
    asm volatile("cp.async.cg.shared.global [%0], [%1], 16;"
                 :: "r"(dst), "l"(src) : "memory");
}
__device__ __forceinline__ void cp_commit() {
    asm volatile("cp.async.commit_group;" ::: "memory");
}
template <int N>
__device__ __forceinline__ void cp_wait() {
    asm volatile("cp.async.wait_group %0;" :: "n"(N) : "memory");
}

__device__ __forceinline__ void ldsm4(uint32_t* r, uint32_t addr) {
    asm volatile("ldmatrix.sync.aligned.m8n8.x4.shared.b16 {%0,%1,%2,%3}, [%4];"
                 : "=r"(r[0]), "=r"(r[1]), "=r"(r[2]), "=r"(r[3]) : "r"(addr));
}
__device__ __forceinline__ void ldsm4t(uint32_t* r, uint32_t addr) {
    asm volatile("ldmatrix.sync.aligned.m8n8.x4.trans.shared.b16 {%0,%1,%2,%3}, [%4];"
                 : "=r"(r[0]), "=r"(r[1]), "=r"(r[2]), "=r"(r[3]) : "r"(addr));
}

__device__ __forceinline__ void mma16816(float* c, const uint32_t* a,
                                         uint32_t b0, uint32_t b1) {
    asm volatile(
        "mma.sync.aligned.m16n8k16.row.col.f32.bf16.bf16.f32 "
        "{%0,%1,%2,%3}, {%4,%5,%6,%7}, {%8,%9}, {%0,%1,%2,%3};"
        : "+f"(c[0]), "+f"(c[1]), "+f"(c[2]), "+f"(c[3])
        : "r"(a[0]), "r"(a[1]), "r"(a[2]), "r"(a[3]), "r"(b0), "r"(b1));
}

// split (x,y) fp32 pair into packed bf16x2 hi and residual lo
__device__ __forceinline__ void split2(float x, float y, uint32_t& hi, uint32_t& lo) {
    __nv_bfloat162 h = __floats2bfloat162_rn(x, y);
    float2 f = __bfloat1622float2(h);
    __nv_bfloat162 l = __floats2bfloat162_rn(x - f.x, y - f.y);
    hi = *reinterpret_cast<uint32_t*>(&h);
    lo = *reinterpret_cast<uint32_t*>(&l);
}

// ---------------------------------------------------------------------------
// fp32 -> (hi, lo bf16) split conversion
// ---------------------------------------------------------------------------
__global__ __launch_bounds__(256) void cvt_kernel(
    const float* __restrict__ src, bf16* __restrict__ hi,
    bf16* __restrict__ lo, int n4)
{
    int i = blockIdx.x * blockDim.x + threadIdx.x;
    if (i >= n4) return;
    float4 v = ((const float4*)src)[i];
    uint32_t h0, l0, h1, l1;
    split2(v.x, v.y, h0, l0);
    split2(v.z, v.w, h1, l1);
    ((uint32_t*)hi)[i * 2 + 0] = h0;
    ((uint32_t*)hi)[i * 2 + 1] = h1;
    ((uint32_t*)lo)[i * 2 + 0] = l0;
    ((uint32_t*)lo)[i * 2 + 1] = l1;
}

// ---------------------------------------------------------------------------
// Projection GEMM (mma.sync, split bf16):
//   out[m][n] = sum_k X[m][k] W[n][k] ; then (out + bias[n]) * scale,
//   split to hi/lo bf16, stored [b,h,s,d].
// CTA tile 128x128, K-chunk 32, 8 warps (2m x 4n), warp tile 64x32.
// smem pitch: 32 k * 2B = 64B padded to 80B (odd multiple of 16B).
// ---------------------------------------------------------------------------
#define P_PITCH 80
#define P_TILE  (128 * P_PITCH)       // 10240 B
#define P_STAGE (4 * P_TILE)          // 40960 B: [Ah, Al, Bh, Bl]
#define P_SMEM  (2 * P_STAGE)         // 81920 B

__global__ __launch_bounds__(256, 1) void proj_mma(
    const bf16* __restrict__ Whi, const bf16* __restrict__ Wlo,
    const float* __restrict__ bias, float scale,
    bf16* __restrict__ Dhi, bf16* __restrict__ Dlo)
{
    extern __shared__ char sm[];
    const uint32_t smb = smem_u32(sm);
    const int tid  = threadIdx.x;
    const int lane = tid & 31;
    const int wid  = tid >> 5;
    const int wm   = wid >> 2;        // 0..1
    const int wn   = wid & 3;         // 0..3
    const int m0   = blockIdx.y * 128;
    const int n0   = blockIdx.x * 128;

    // loader mapping: row = tid>>1 (0..127), half = tid&1 -> 16 k each
    const int lr = tid >> 1;
    const int lh = tid & 1;
    const bf16* gxh = g_xhi + (size_t)(m0 + lr) * E_ + lh * 16;
    const bf16* gxl = g_xlo + (size_t)(m0 + lr) * E_ + lh * 16;
    const bf16* gwh = Whi   + (size_t)(n0 + lr) * E_ + lh * 16;
    const bf16* gwl = Wlo   + (size_t)(n0 + lr) * E_ + lh * 16;
    const uint32_t soff = (uint32_t)(lr * P_PITCH + lh * 32);

#define P_LOAD(ch, stg) do {                                                  \
    uint32_t sb = smb + (stg) * P_STAGE + soff;                               \
    int k0 = (ch) * 32;                                                       \
    cp16(sb + 0 * P_TILE +  0, gxh + k0);                                     \
    cp16(sb + 0 * P_TILE + 16, gxh + k0 + 8);                                 \
    cp16(sb + 1 * P_TILE +  0, gxl + k0);                                     \
    cp16(sb + 1 * P_TILE + 16, gxl + k0 + 8);                                 \
    cp16(sb + 2 * P_TILE +  0, gwh + k0);                                     \
    cp16(sb + 2 * P_TILE + 16, gwh + k0 + 8);                                 \
    cp16(sb + 3 * P_TILE +  0, gwl + k0);                                     \
    cp16(sb + 3 * P_TILE + 16, gwl + k0 + 8);                                 \
} while (0)

    float acc[4][4][4];
#pragma unroll
    for (int i = 0; i < 4; i++)
#pragma unroll
        for (int j = 0; j < 4; j++)
#pragma unroll
            for (int c = 0; c < 4; c++) acc[i][j][c] = 0.f;

    P_LOAD(0, 0); cp_commit();
    P_LOAD(1, 1); cp_commit();

    const uint32_t a_off = (uint32_t)((wm * 64 + (lane & 15)) * P_PITCH + (lane >> 4) * 16);
    const uint32_t b_off = (uint32_t)((wn * 32 + (lane & 7)) * P_PITCH + (lane >> 3) * 16);

    for (int ch = 0; ch < 32; ch++) {
        if (ch >= 30) cp_wait<0>(); else cp_wait<1>();
        __syncthreads();

        const uint32_t sb = smb + (ch & 1) * P_STAGE;

        uint32_t bh[4][4], bl[4][4];
#pragma unroll
        for (int nf = 0; nf < 4; nf++) {
            uint32_t ba = sb + b_off + (uint32_t)(nf * 8 * P_PITCH);
            ldsm4(bh[nf], ba + 2 * P_TILE);
            ldsm4(bl[nf], ba + 3 * P_TILE);
        }

#pragma unroll
        for (int kf = 0; kf < 2; kf++) {
            uint32_t ah[4][4], al[4][4];
#pragma unroll
            for (int mf = 0; mf < 4; mf++) {
                uint32_t aa = sb + a_off + (uint32_t)(mf * 16 * P_PITCH + kf * 32);
                ldsm4(ah[mf], aa);
                ldsm4(al[mf], aa + P_TILE);
            }
#pragma unroll
            for (int mf = 0; mf < 4; mf++)
#pragma unroll
                for (int nf = 0; nf < 4; nf++) {
                    mma16816(acc[mf][nf], ah[mf], bh[nf][kf*2], bh[nf][kf*2+1]);
                    mma16816(acc[mf][nf], ah[mf], bl[nf][kf*2], bl[nf][kf*2+1]);
                    mma16816(acc[mf][nf], al[mf], bh[nf][kf*2], bh[nf][kf*2+1]);
                }
        }
        __syncthreads();
        if (ch + 2 < 32) { P_LOAD(ch + 2, ch & 1); cp_commit(); }
    }

    // epilogue: bias, scale, split, scatter to [b,h,s,d]
#pragma unroll
    for (int mf = 0; mf < 4; mf++) {
        int r0 = m0 + wm * 64 + mf * 16 + (lane >> 2);
        int r1 = r0 + 8;
        int b0i = r0 >> 11, s0i = r0 & (S_ - 1);
        int b1i = r1 >> 11, s1i = r1 & (S_ - 1);
#pragma unroll
        for (int nf = 0; nf < 4; nf++) {
            int n = n0 + wn * 32 + nf * 8 + 2 * (lane & 3);
            float2 bv = *(const float2*)&bias[n];
            float v00 = (acc[mf][nf][0] + bv.x) * scale;
            float v01 = (acc[mf][nf][1] + bv.y) * scale;
            float v10 = (acc[mf][nf][2] + bv.x) * scale;
            float v11 = (acc[mf][nf][3] + bv.y) * scale;
            uint32_t h0, l0, h1, l1;
            split2(v00, v01, h0, l0);
            split2(v10, v11, h1, l1);
            int h = n >> 6, d = n & 63;
            size_t i0 = (((size_t)b0i * H_ + h) * S_ + s0i) * D_ + d;
            size_t i1 = (((size_t)b1i * H_ + h) * S_ + s1i) * D_ + d;
            *(uint32_t*)(Dhi + i0) = h0;
            *(uint32_t*)(Dlo + i0) = l0;
            *(uint32_t*)(Dhi + i1) = h1;
            *(uint32_t*)(Dlo + i1) = l1;
        }
    }
#undef P_LOAD
}

// ---------------------------------------------------------------------------
// Attention (mma.sync, split bf16, inverted-band mask, no online max):
// CTA: 128 queries x (b,h); 8 warps, warp owns 16 q-rows.
// KV tile 64, double-buffered cp.async. pitch 144B (odd multiple of 16B).
// ---------------------------------------------------------------------------
#define A_PITCH 144
#define A_KV_TILE (64 * A_PITCH)       // 9216 B
#define A_STAGE   (4 * A_KV_TILE)      // 36864: [Kh, Kl, Vh, Vl]
#define A_SMEM    (2 * A_STAGE)        // 73728

__global__ __launch_bounds__(256, 1) void attn_mma(float* __restrict__ out)
{
    extern __shared__ char sm[];
    const uint32_t smb = smem_u32(sm);
    const int tid  = threadIdx.x;
    const int lane = tid & 31;
    const int w    = tid >> 5;               // 0..7
    const int q0   = blockIdx.x * 128;
    const int h    = blockIdx.y;
    const int b    = blockIdx.z;

    const size_t base = ((size_t)b * H_ + h) * S_ * D_;
    const bf16* Qh = g_qhi + base;
    const bf16* Ql = g_qlo + base;
    const bf16* Kh = g_khi + base;
    const bf16* Kl = g_klo + base;
    const bf16* Vh = g_vhi + base;
    const bf16* Vl = g_vlo + base;

    // ---- stage Q into smem (pitch 144), extract fragments, release smem ----
    {
        int r = tid >> 1;
        int c = (tid & 1) * 4;                 // 4 chunks of 16B each
        const bf16* qh = Qh + (size_t)(q0 + r) * D_ + c * 8;
        const bf16* ql = Ql + (size_t)(q0 + r) * D_ + c * 8;
        uint32_t sh = smb + (uint32_t)(r * A_PITCH + c * 16);
#pragma unroll
        for (int i = 0; i < 4; i++) {
            cp16(sh + i * 16,         qh + i * 8);
            cp16(sh + i * 16 + 18432, ql + i * 8);
        }
        cp_commit();
        cp_wait<0>();
        __syncthreads();
    }

    uint32_t qh_[4][4], ql_[4][4];
    {
        uint32_t qa = smb + (uint32_t)((w * 16 + (lane & 15)) * A_PITCH + (lane >> 4) * 16);
#pragma unroll
        for (int kf = 0; kf < 4; kf++) {
            ldsm4(qh_[kf], qa + kf * 32);
            ldsm4(ql_[kf], qa + kf * 32 + 18432);
        }
    }
    __syncthreads();

    // ---- KV loader mapping ----
    const int lr = tid >> 2;                   // 0..63
    const int lc = (tid & 3) * 2;              // 2 chunks per tile
    const uint32_t kvoff = (uint32_t)(lr * A_PITCH + lc * 16);

#define KV_LOAD(ch, stg) do {                                                  \
    size_t g = (size_t)((ch) * 64 + lr) * D_ + lc * 8;                         \
    uint32_t sb = smb + (stg) * A_STAGE + kvoff;                               \
    cp16(sb + 0 * A_KV_TILE,      Kh + g);                                     \
    cp16(sb + 0 * A_KV_TILE + 16, Kh + g + 8);                                 \
    cp16(sb + 1 * A_KV_TILE,      Kl + g);                                     \
    cp16(sb + 1 * A_KV_TILE + 16, Kl + g + 8);                                 \
    cp16(sb + 2 * A_KV_TILE,      Vh + g);                                     \
    cp16(sb + 2 * A_KV_TILE + 16, Vh + g + 8);                                 \
    cp16(sb + 3 * A_KV_TILE,      Vl + g);                                     \
    cp16(sb + 3 * A_KV_TILE + 16, Vl + g + 8);                                 \
} while (0)

    float o[8][4];
#pragma unroll
    for (int i = 0; i < 8; i++)
#pragma unroll
        for (int c = 0; c < 4; c++) o[i][c] = 0.f;
    float lsum0 = 0.f, lsum1 = 0.f;

    KV_LOAD(0, 0); cp_commit();
    KV_LOAD(1, 1); cp_commit();

    const int r0 = q0 + w * 16 + (lane >> 2);
    const int r1 = r0 + 8;
    const uint32_t kb_off = (uint32_t)((lane & 7) * A_PITCH + (lane >> 3) * 16);
    const uint32_t vb_off = (uint32_t)((lane & 15) * A_PITCH + (lane >> 4) * 16);

    for (int ch = 0; ch < 32; ch++) {
        if (ch >= 30) cp_wait<0>(); else cp_wait<1>();
        __syncthreads();

        const uint32_t sb = smb + (ch & 1) * A_STAGE;
        const int kt = ch * 64;

        // ---- S = Q K^T (split: QhKh + QhKl + QlKh) ----
        float s[8][4];
#pragma unroll
        for (int i = 0; i < 8; i++)
#pragma unroll
            for (int c = 0; c < 4; c++) s[i][c] = 0.f;

#pragma unroll
        for (int nf = 0; nf < 8; nf++) {
            uint32_t ka = sb + kb_off + (uint32_t)(nf * 8 * A_PITCH);
#pragma unroll
            for (int p = 0; p < 2; p++) {
                uint32_t kh4[4], kl4[4];
                ldsm4(kh4, ka + p * 64);
                ldsm4(kl4, ka + p * 64 + A_KV_TILE);
                mma16816(s[nf], qh_[2*p],   kh4[0], kh4[1]);
                mma16816(s[nf], qh_[2*p],   kl4[0], kl4[1]);
                mma16816(s[nf], ql_[2*p],   kh4[0], kh4[1]);
                mma16816(s[nf], qh_[2*p+1], kh4[2], kh4[3]);
                mma16816(s[nf], qh_[2*p+1], kl4[2], kl4[3]);
                mma16816(s[nf], ql_[2*p+1], kh4[2], kh4[3]);
            }
        }

        // ---- mask (inverted band) + exp + row sums ----
        bool need_mask = (kt + 63 >= q0 - WIN) && (kt <= q0 + 127 + WIN);
        if (need_mask) {
#pragma unroll
            for (int nf = 0; nf < 8; nf++) {
                int kcol = kt + nf * 8 + 2 * (lane & 3);
#pragma unroll
                for (int c = 0; c < 4; c++) {
                    int qg = (c < 2) ? r0 : r1;
                    int kg = kcol + (c & 1);
                    int dd = qg - kg;
                    float e = (dd <= WIN && dd >= -WIN) ? 0.f : __expf(s[nf][c]);
                    s[nf][c] = e;
                    if (c < 2) lsum0 += e; else lsum1 += e;
                }
            }
        } else {
#pragma unroll
            for (int nf = 0; nf < 8; nf++)
#pragma unroll
                for (int c = 0; c < 4; c++) {
                    float e = __expf(s[nf][c]);
                    s[nf][c] = e;
                    if (c < 2) lsum0 += e; else lsum1 += e;
                }
        }

        // ---- O += P V (split: PhVh + PhVl + PlVh) ----
#pragma unroll
        for (int kf = 0; kf < 4; kf++) {
            uint32_t Ah[4], Al[4];
            split2(s[2*kf][0],   s[2*kf][1],   Ah[0], Al[0]);
            split2(s[2*kf][2],   s[2*kf][3],   Ah[1], Al[1]);
            split2(s[2*kf+1][0], s[2*kf+1][1], Ah[2], Al[2]);
            split2(s[2*kf+1][2], s[2*kf+1][3], Ah[3], Al[3]);
            uint32_t va = sb + 2 * A_KV_TILE + vb_off + (uint32_t)(kf * 16 * A_PITCH);
#pragma unroll
            for (int np = 0; np < 4; np++) {
                uint32_t vh4[4], vl4[4];
                ldsm4t(vh4, va + np * 32);
                ldsm4t(vl4, va + np * 32 + A_KV_TILE);
                mma16816(o[2*np],   Ah, vh4[0], vh4[1]);
                mma16816(o[2*np],   Ah, vl4[0], vl4[1]);
                mma16816(o[2*np],   Al, vh4[0], vh4[1]);
                mma16816(o[2*np+1], Ah, vh4[2], vh4[3]);
                mma16816(o[2*np+1], Ah, vl4[2], vl4[3]);
                mma16816(o[2*np+1], Al, vh4[2], vh4[3]);
            }
        }

        __syncthreads();
        if (ch + 2 < 32) { KV_LOAD(ch + 2, ch & 1); cp_commit(); }
    }

    // ---- reduce row sums across the quad (lanes differing in lane&3) ----
    lsum0 += __shfl_xor_sync(0xffffffffu, lsum0, 1);
    lsum0 += __shfl_xor_sync(0xffffffffu, lsum0, 2);
    lsum1 += __shfl_xor_sync(0xffffffffu, lsum1, 1);
    lsum1 += __shfl_xor_sync(0xffffffffu, lsum1, 2);
    float inv0 = 1.0f / lsum0;
    float inv1 = 1.0f / lsum1;

    // ---- store out[b, s, h*64 + d] ----
#pragma unroll
    for (int nf = 0; nf < 8; nf++) {
        int d = h * 64 + nf * 8 + 2 * (lane & 3);
        float2 v0 = make_float2(o[nf][0] * inv0, o[nf][1] * inv0);
        float2 v1 = make_float2(o[nf][2] * inv1, o[nf][3] * inv1);
        *(float2*)&out[((size_t)b * S_ + r0) * E_ + d] = v0;
        *(float2*)&out[((size_t)b * S_ + r1) * E_ + d] = v1;
    }
#undef KV_LOAD
}

// ---------------------------------------------------------------------------
extern "C" void kernel_launch(void* const* d_in, const int* in_sizes, int n_in,
                              void* d_out, int out_size)
{
    const float* X  = (const float*)d_in[0];
    const float* Wq = (const float*)d_in[1];
    const float* bq = (const float*)d_in[2];
    const float* Wk = (const float*)d_in[3];
    const float* bk = (const float*)d_in[4];
    const float* Wv = (const float*)d_in[5];
    const float* bv = (const float*)d_in[6];
    float* out = (float*)d_out;

    bf16 *xhi, *xlo, *wqh, *wql, *wkh, *wkl, *wvh, *wvl;
    bf16 *qhi, *qlo, *khi, *klo, *vhi, *vlo;
    cudaGetSymbolAddress((void**)&xhi, g_xhi);
    cudaGetSymbolAddress((void**)&xlo, g_xlo);
    cudaGetSymbolAddress((void**)&wqh, g_wqhi);
    cudaGetSymbolAddress((void**)&wql, g_wqlo);
    cudaGetSymbolAddress((void**)&wkh, g_wkhi);
    cudaGetSymbolAddress((void**)&wkl, g_wklo);
    cudaGetSymbolAddress((void**)&wvh, g_wvhi);
    cudaGetSymbolAddress((void**)&wvl, g_wvlo);
    cudaGetSymbolAddress((void**)&qhi, g_qhi);
    cudaGetSymbolAddress((void**)&qlo, g_qlo);
    cudaGetSymbolAddress((void**)&khi, g_khi);
    cudaGetSymbolAddress((void**)&klo, g_klo);
    cudaGetSymbolAddress((void**)&vhi, g_vhi);
    cudaGetSymbolAddress((void**)&vlo, g_vlo);

    // split conversions
    cvt_kernel<<<(MS_*E_/4 + 255)/256, 256>>>(X,  xhi, xlo, MS_*E_/4);
    cvt_kernel<<<(E_*E_/4 + 255)/256, 256>>>(Wq, wqh, wql, E_*E_/4);
    cvt_kernel<<<(E_*E_/4 + 255)/256, 256>>>(Wk, wkh, wkl, E_*E_/4);
    cvt_kernel<<<(E_*E_/4 + 255)/256, 256>>>(Wv, wvh, wvl, E_*E_/4);

    cudaFuncSetAttribute(proj_mma,
                         cudaFuncAttributeMaxDynamicSharedMemorySize, P_SMEM);
    dim3 pgrid(E_ / 128, MS_ / 128);   // (8, 32)
    proj_mma<<<pgrid, 256, P_SMEM>>>(wqh, wql, bq, 0.125f, qhi, qlo);
    proj_mma<<<pgrid, 256, P_SMEM>>>(wkh, wkl, bk, 1.0f,   khi, klo);
    proj_mma<<<pgrid, 256, P_SMEM>>>(wvh, wvl, bv, 1.0f,   vhi, vlo);

    cudaFuncSetAttribute(attn_mma,
                         cudaFuncAttributeMaxDynamicSharedMemorySize, A_SMEM);
    dim3 agrid(S_ / 128, H_, B_);      // (16, 16, 2)
    attn_mma<<<agrid, 256, A_SMEM>>>(out);
}

// round 4
// speedup vs baseline: 4.5783x; 1.7427x over previous
#include <cuda_runtime.h>
#include <cuda_fp16.h>
#include <cstdint>

#define B_   2
#define S_   2048
#define E_   1024
#define H_   16
#define D_   64
#define WIN  3
#define MS_  (B_*S_)          // 4096 rows

typedef __half f16;

// ---------------------------------------------------------------------------
// Device-global scratch (allocation-free)
// ---------------------------------------------------------------------------
__device__ f16 g_xh[MS_*E_], g_xl[MS_*E_];          // X split (hi/lo fp16)
__device__ f16 g_wq[E_*E_], g_wk[E_*E_];            // Wq, Wk single fp16
__device__ f16 g_wvh[E_*E_], g_wvl[E_*E_];          // Wv split
__device__ f16 g_qh[B_*H_*S_*D_];                   // Q (prescaled 1/8), single
__device__ f16 g_kh[B_*H_*S_*D_];                   // K single
__device__ f16 g_vh[B_*H_*S_*D_], g_vl[B_*H_*S_*D_]; // V split

// ---------------------------------------------------------------------------
// Helpers (plain sm_80-level PTX: cp.async / ldmatrix / mma.sync)
// ---------------------------------------------------------------------------
__device__ __forceinline__ uint32_t smem_u32(const void* p) {
    uint32_t a;
    asm("{ .reg .u64 t; cvta.to.shared.u64 t, %1; cvt.u32.u64 %0, t; }"
        : "=r"(a) : "l"(p));
    return a;
}
__device__ __forceinline__ void cp16(uint32_t dst, const void* src) {
    asm volatile("cp.async.cg.shared.global [%0], [%1], 16;"
                 :: "r"(dst), "l"(src) : "memory");
}
__device__ __forceinline__ void cp_commit() {
    asm volatile("cp.async.commit_group;" ::: "memory");
}
template <int N>
__device__ __forceinline__ void cp_wait() {
    asm volatile("cp.async.wait_group %0;" :: "n"(N) : "memory");
}
__device__ __forceinline__ void ldsm4(uint32_t* r, uint32_t addr) {
    asm volatile("ldmatrix.sync.aligned.m8n8.x4.shared.b16 {%0,%1,%2,%3}, [%4];"
                 : "=r"(r[0]), "=r"(r[1]), "=r"(r[2]), "=r"(r[3]) : "r"(addr));
}
__device__ __forceinline__ void ldsm4t(uint32_t* r, uint32_t addr) {
    asm volatile("ldmatrix.sync.aligned.m8n8.x4.trans.shared.b16 {%0,%1,%2,%3}, [%4];"
                 : "=r"(r[0]), "=r"(r[1]), "=r"(r[2]), "=r"(r[3]) : "r"(addr));
}
__device__ __forceinline__ void mma16816(float* c, const uint32_t* a,
                                         uint32_t b0, uint32_t b1) {
    asm volatile(
        "mma.sync.aligned.m16n8k16.row.col.f32.f16.f16.f32 "
        "{%0,%1,%2,%3}, {%4,%5,%6,%7}, {%8,%9}, {%0,%1,%2,%3};"
        : "+f"(c[0]), "+f"(c[1]), "+f"(c[2]), "+f"(c[3])
        : "r"(a[0]), "r"(a[1]), "r"(a[2]), "r"(a[3]), "r"(b0), "r"(b1));
}

__device__ __forceinline__ uint32_t pack_h2(float x, float y) {
    __half2 h = __floats2half2_rn(x, y);
    return *reinterpret_cast<uint32_t*>(&h);
}
// fp32 pair -> fp16 hi pair + fp16 residual pair
__device__ __forceinline__ void split2h(float x, float y, uint32_t& hi, uint32_t& lo) {
    __half2 h = __floats2half2_rn(x, y);
    float2 f = __half22float2(h);
    __half2 l = __floats2half2_rn(x - f.x, y - f.y);
    hi = *reinterpret_cast<uint32_t*>(&h);
    lo = *reinterpret_cast<uint32_t*>(&l);
}

// ---------------------------------------------------------------------------
// Conversions
// ---------------------------------------------------------------------------
__global__ __launch_bounds__(256) void cvt_pair(
    const float* __restrict__ src, f16* __restrict__ hi,
    f16* __restrict__ lo, int n4)
{
    int i = blockIdx.x * blockDim.x + threadIdx.x;
    if (i >= n4) return;
    float4 v = ((const float4*)src)[i];
    uint32_t h0, l0, h1, l1;
    split2h(v.x, v.y, h0, l0);
    split2h(v.z, v.w, h1, l1);
    ((uint32_t*)hi)[i * 2 + 0] = h0;
    ((uint32_t*)hi)[i * 2 + 1] = h1;
    ((uint32_t*)lo)[i * 2 + 0] = l0;
    ((uint32_t*)lo)[i * 2 + 1] = l1;
}

__global__ __launch_bounds__(256) void cvt_single(
    const float* __restrict__ src, f16* __restrict__ dst, int n4)
{
    int i = blockIdx.x * blockDim.x + threadIdx.x;
    if (i >= n4) return;
    float4 v = ((const float4*)src)[i];
    ((uint32_t*)dst)[i * 2 + 0] = pack_h2(v.x, v.y);
    ((uint32_t*)dst)[i * 2 + 1] = pack_h2(v.z, v.w);
}

// ---------------------------------------------------------------------------
// Shared tiling constants (both proj kernels)
// CTA 128x128, K-chunk 32, 8 warps (2m x 4n), warp tile 64x32, pitch 80B.
// ---------------------------------------------------------------------------
#define P_PITCH 80
#define P_TILE  (128 * P_PITCH)        // 10240 B

// ---------------------------------------------------------------------------
// Single-precision-pass projection (Q, K): 1 mma per fragment.
// smem: 2 stages x [Ah, Bh] = 40960 B -> 2 CTAs/SM.
// ---------------------------------------------------------------------------
#define P1_STAGE (2 * P_TILE)
#define P1_SMEM  (2 * P1_STAGE)        // 40960

__global__ __launch_bounds__(256, 2) void proj_single(
    const f16* __restrict__ W, const float* __restrict__ bias, float scale,
    f16* __restrict__ Dst)
{
    extern __shared__ char sm[];
    const uint32_t smb = smem_u32(sm);
    const int tid  = threadIdx.x;
    const int lane = tid & 31;
    const int wid  = tid >> 5;
    const int wm   = wid >> 2;
    const int wn   = wid & 3;
    const int m0   = blockIdx.y * 128;
    const int n0   = blockIdx.x * 128;

    const int lr = tid >> 1;
    const int lh = tid & 1;
    const f16* gx = g_xh + (size_t)(m0 + lr) * E_ + lh * 16;
    const f16* gw = W    + (size_t)(n0 + lr) * E_ + lh * 16;
    const uint32_t soff = (uint32_t)(lr * P_PITCH + lh * 32);

#define P1_LOAD(ch, stg) do {                                                 \
    uint32_t sb = smb + (stg) * P1_STAGE + soff;                              \
    int k0 = (ch) * 32;                                                       \
    cp16(sb +  0, gx + k0);  cp16(sb + 16, gx + k0 + 8);                      \
    cp16(sb + P_TILE +  0, gw + k0);  cp16(sb + P_TILE + 16, gw + k0 + 8);    \
} while (0)

    float acc[4][4][4];
#pragma unroll
    for (int i = 0; i < 4; i++)
#pragma unroll
        for (int j = 0; j < 4; j++)
#pragma unroll
            for (int c = 0; c < 4; c++) acc[i][j][c] = 0.f;

    P1_LOAD(0, 0); cp_commit();
    P1_LOAD(1, 1); cp_commit();

    const uint32_t a_off = (uint32_t)((wm * 64 + (lane & 15)) * P_PITCH + (lane >> 4) * 16);
    const uint32_t b_off = (uint32_t)((wn * 32 + (lane & 7)) * P_PITCH + (lane >> 3) * 16);

    for (int ch = 0; ch < 32; ch++) {
        if (ch >= 30) cp_wait<0>(); else cp_wait<1>();
        __syncthreads();
        const uint32_t sb = smb + (ch & 1) * P1_STAGE;

        uint32_t bh[4][4];
#pragma unroll
        for (int nf = 0; nf < 4; nf++)
            ldsm4(bh[nf], sb + P_TILE + b_off + (uint32_t)(nf * 8 * P_PITCH));

#pragma unroll
        for (int kf = 0; kf < 2; kf++) {
            uint32_t ah[4][4];
#pragma unroll
            for (int mf = 0; mf < 4; mf++)
                ldsm4(ah[mf], sb + a_off + (uint32_t)(mf * 16 * P_PITCH + kf * 32));
#pragma unroll
            for (int mf = 0; mf < 4; mf++)
#pragma unroll
                for (int nf = 0; nf < 4; nf++)
                    mma16816(acc[mf][nf], ah[mf], bh[nf][kf*2], bh[nf][kf*2+1]);
        }
        __syncthreads();
        if (ch + 2 < 32) { P1_LOAD(ch + 2, ch & 1); cp_commit(); }
    }

#pragma unroll
    for (int mf = 0; mf < 4; mf++) {
        int r0 = m0 + wm * 64 + mf * 16 + (lane >> 2);
        int r1 = r0 + 8;
        int b0i = r0 >> 11, s0i = r0 & (S_ - 1);
        int b1i = r1 >> 11, s1i = r1 & (S_ - 1);
#pragma unroll
        for (int nf = 0; nf < 4; nf++) {
            int n = n0 + wn * 32 + nf * 8 + 2 * (lane & 3);
            float2 bv = *(const float2*)&bias[n];
            uint32_t p0 = pack_h2((acc[mf][nf][0] + bv.x) * scale,
                                  (acc[mf][nf][1] + bv.y) * scale);
            uint32_t p1 = pack_h2((acc[mf][nf][2] + bv.x) * scale,
                                  (acc[mf][nf][3] + bv.y) * scale);
            int h = n >> 6, d = n & 63;
            size_t i0 = (((size_t)b0i * H_ + h) * S_ + s0i) * D_ + d;
            size_t i1 = (((size_t)b1i * H_ + h) * S_ + s1i) * D_ + d;
            *(uint32_t*)(Dst + i0) = p0;
            *(uint32_t*)(Dst + i1) = p1;
        }
    }
#undef P1_LOAD
}

// ---------------------------------------------------------------------------
// Split-precision projection (V): 3 mma per fragment, hi/lo fp16 output.
// smem: 2 stages x [Ah, Al, Bh, Bl] = 81920 B -> 1 CTA/SM.
// ---------------------------------------------------------------------------
#define P3_STAGE (4 * P_TILE)
#define P3_SMEM  (2 * P3_STAGE)        // 81920

__global__ __launch_bounds__(256, 1) void proj_split(
    const f16* __restrict__ Whi, const f16* __restrict__ Wlo,
    const float* __restrict__ bias,
    f16* __restrict__ Dhi, f16* __restrict__ Dlo)
{
    extern __shared__ char sm[];
    const uint32_t smb = smem_u32(sm);
    const int tid  = threadIdx.x;
    const int lane = tid & 31;
    const int wid  = tid >> 5;
    const int wm   = wid >> 2;
    const int wn   = wid & 3;
    const int m0   = blockIdx.y * 128;
    const int n0   = blockIdx.x * 128;

    const int lr = tid >> 1;
    const int lh = tid & 1;
    const f16* gxh = g_xh + (size_t)(m0 + lr) * E_ + lh * 16;
    const f16* gxl = g_xl + (size_t)(m0 + lr) * E_ + lh * 16;
    const f16* gwh = Whi  + (size_t)(n0 + lr) * E_ + lh * 16;
    const f16* gwl = Wlo  + (size_t)(n0 + lr) * E_ + lh * 16;
    const uint32_t soff = (uint32_t)(lr * P_PITCH + lh * 32);

#define P3_LOAD(ch, stg) do {                                                 \
    uint32_t sb = smb + (stg) * P3_STAGE + soff;                              \
    int k0 = (ch) * 32;                                                       \
    cp16(sb + 0 * P_TILE +  0, gxh + k0); cp16(sb + 0 * P_TILE + 16, gxh + k0 + 8); \
    cp16(sb + 1 * P_TILE +  0, gxl + k0); cp16(sb + 1 * P_TILE + 16, gxl + k0 + 8); \
    cp16(sb + 2 * P_TILE +  0, gwh + k0); cp16(sb + 2 * P_TILE + 16, gwh + k0 + 8); \
    cp16(sb + 3 * P_TILE +  0, gwl + k0); cp16(sb + 3 * P_TILE + 16, gwl + k0 + 8); \
} while (0)

    float acc[4][4][4];
#pragma unroll
    for (int i = 0; i < 4; i++)
#pragma unroll
        for (int j = 0; j < 4; j++)
#pragma unroll
            for (int c = 0; c < 4; c++) acc[i][j][c] = 0.f;

    P3_LOAD(0, 0); cp_commit();
    P3_LOAD(1, 1); cp_commit();

    const uint32_t a_off = (uint32_t)((wm * 64 + (lane & 15)) * P_PITCH + (lane >> 4) * 16);
    const uint32_t b_off = (uint32_t)((wn * 32 + (lane & 7)) * P_PITCH + (lane >> 3) * 16);

    for (int ch = 0; ch < 32; ch++) {
        if (ch >= 30) cp_wait<0>(); else cp_wait<1>();
        __syncthreads();
        const uint32_t sb = smb + (ch & 1) * P3_STAGE;

        uint32_t bh[4][4], bl[4][4];
#pragma unroll
        for (int nf = 0; nf < 4; nf++) {
            uint32_t ba = sb + b_off + (uint32_t)(nf * 8 * P_PITCH);
            ldsm4(bh[nf], ba + 2 * P_TILE);
            ldsm4(bl[nf], ba + 3 * P_TILE);
        }
#pragma unroll
        for (int kf = 0; kf < 2; kf++) {
            uint32_t ah[4][4], al[4][4];
#pragma unroll
            for (int mf = 0; mf < 4; mf++) {
                uint32_t aa = sb + a_off + (uint32_t)(mf * 16 * P_PITCH + kf * 32);
                ldsm4(ah[mf], aa);
                ldsm4(al[mf], aa + P_TILE);
            }
#pragma unroll
            for (int mf = 0; mf < 4; mf++)
#pragma unroll
                for (int nf = 0; nf < 4; nf++) {
                    mma16816(acc[mf][nf], ah[mf], bh[nf][kf*2], bh[nf][kf*2+1]);
                    mma16816(acc[mf][nf], ah[mf], bl[nf][kf*2], bl[nf][kf*2+1]);
                    mma16816(acc[mf][nf], al[mf], bh[nf][kf*2], bh[nf][kf*2+1]);
                }
        }
        __syncthreads();
        if (ch + 2 < 32) { P3_LOAD(ch + 2, ch & 1); cp_commit(); }
    }

#pragma unroll
    for (int mf = 0; mf < 4; mf++) {
        int r0 = m0 + wm * 64 + mf * 16 + (lane >> 2);
        int r1 = r0 + 8;
        int b0i = r0 >> 11, s0i = r0 & (S_ - 1);
        int b1i = r1 >> 11, s1i = r1 & (S_ - 1);
#pragma unroll
        for (int nf = 0; nf < 4; nf++) {
            int n = n0 + wn * 32 + nf * 8 + 2 * (lane & 3);
            float2 bv = *(const float2*)&bias[n];
            uint32_t h0, l0, h1, l1;
            split2h(acc[mf][nf][0] + bv.x, acc[mf][nf][1] + bv.y, h0, l0);
            split2h(acc[mf][nf][2] + bv.x, acc[mf][nf][3] + bv.y, h1, l1);
            int h = n >> 6, d = n & 63;
            size_t i0 = (((size_t)b0i * H_ + h) * S_ + s0i) * D_ + d;
            size_t i1 = (((size_t)b1i * H_ + h) * S_ + s1i) * D_ + d;
            *(uint32_t*)(Dhi + i0) = h0;
            *(uint32_t*)(Dlo + i0) = l0;
            *(uint32_t*)(Dhi + i1) = h1;
            *(uint32_t*)(Dlo + i1) = l1;
        }
    }
#undef P3_LOAD
}

// ---------------------------------------------------------------------------
// Attention: fp16 single Q,K,P; split V. Inverted-band mask, no online max.
// CTA: 128 q x (b,h); 8 warps x 16 q-rows; KV tile 64, double-buffered.
// smem: 2 stages x [Kh, Vh, Vl] x 9216 = 55296 -> 2 CTAs/SM.
// ---------------------------------------------------------------------------
#define A_PITCH   144
#define A_KV_TILE (64 * A_PITCH)       // 9216
#define A_STAGE   (3 * A_KV_TILE)      // 27648
#define A_SMEM    (2 * A_STAGE)        // 55296

__global__ __launch_bounds__(256, 2) void attn_mma(float* __restrict__ out)
{
    extern __shared__ char sm[];
    const uint32_t smb = smem_u32(sm);
    const int tid  = threadIdx.x;
    const int lane = tid & 31;
    const int w    = tid >> 5;
    const int q0   = blockIdx.x * 128;
    const int h    = blockIdx.y;
    const int b    = blockIdx.z;

    const size_t base = ((size_t)b * H_ + h) * S_ * D_;
    const f16* Qh = g_qh + base;
    const f16* Kh = g_kh + base;
    const f16* Vh = g_vh + base;
    const f16* Vl = g_vl + base;

    // ---- stage Q (hi only), extract fragments, release smem ----
    {
        int r = tid >> 1;
        int c = (tid & 1) * 4;
        const f16* q = Qh + (size_t)(q0 + r) * D_ + c * 8;
        uint32_t sh = smb + (uint32_t)(r * A_PITCH + c * 16);
#pragma unroll
        for (int i = 0; i < 4; i++) cp16(sh + i * 16, q + i * 8);
        cp_commit();
        cp_wait<0>();
        __syncthreads();
    }
    uint32_t qf[4][4];
    {
        uint32_t qa = smb + (uint32_t)((w * 16 + (lane & 15)) * A_PITCH + (lane >> 4) * 16);
#pragma unroll
        for (int kf = 0; kf < 4; kf++) ldsm4(qf[kf], qa + kf * 32);
    }
    __syncthreads();

    const int lr = tid >> 2;
    const int lc = (tid & 3) * 2;
    const uint32_t kvoff = (uint32_t)(lr * A_PITCH + lc * 16);

#define KV_LOAD(ch, stg) do {                                                  \
    size_t g = (size_t)((ch) * 64 + lr) * D_ + lc * 8;                         \
    uint32_t sb = smb + (stg) * A_STAGE + kvoff;                               \
    cp16(sb + 0 * A_KV_TILE, Kh + g); cp16(sb + 0 * A_KV_TILE + 16, Kh + g + 8); \
    cp16(sb + 1 * A_KV_TILE, Vh + g); cp16(sb + 1 * A_KV_TILE + 16, Vh + g + 8); \
    cp16(sb + 2 * A_KV_TILE, Vl + g); cp16(sb + 2 * A_KV_TILE + 16, Vl + g + 8); \
} while (0)

    float o[8][4];
#pragma unroll
    for (int i = 0; i < 8; i++)
#pragma unroll
        for (int c = 0; c < 4; c++) o[i][c] = 0.f;
    float lsum0 = 0.f, lsum1 = 0.f;

    KV_LOAD(0, 0); cp_commit();
    KV_LOAD(1, 1); cp_commit();

    const int r0 = q0 + w * 16 + (lane >> 2);
    const int r1 = r0 + 8;
    const uint32_t kb_off = (uint32_t)((lane & 7) * A_PITCH + (lane >> 3) * 16);
    const uint32_t vb_off = (uint32_t)((lane & 15) * A_PITCH + (lane >> 4) * 16);

    for (int ch = 0; ch < 32; ch++) {
        if (ch >= 30) cp_wait<0>(); else cp_wait<1>();
        __syncthreads();

        const uint32_t sb = smb + (ch & 1) * A_STAGE;
        const int kt = ch * 64;

        // ---- S = Q K^T (single pass) ----
        float s[8][4];
#pragma unroll
        for (int i = 0; i < 8; i++)
#pragma unroll
            for (int c = 0; c < 4; c++) s[i][c] = 0.f;

#pragma unroll
        for (int nf = 0; nf < 8; nf++) {
            uint32_t ka = sb + kb_off + (uint32_t)(nf * 8 * A_PITCH);
#pragma unroll
            for (int p = 0; p < 2; p++) {
                uint32_t k4[4];
                ldsm4(k4, ka + p * 64);
                mma16816(s[nf], qf[2*p],   k4[0], k4[1]);
                mma16816(s[nf], qf[2*p+1], k4[2], k4[3]);
            }
        }

        // ---- mask + exp + row sums ----
        bool need_mask = (kt + 63 >= q0 - WIN) && (kt <= q0 + 127 + WIN);
        if (need_mask) {
#pragma unroll
            for (int nf = 0; nf < 8; nf++) {
                int kcol = kt + nf * 8 + 2 * (lane & 3);
#pragma unroll
                for (int c = 0; c < 4; c++) {
                    int qg = (c < 2) ? r0 : r1;
                    int dd = qg - (kcol + (c & 1));
                    float e = (dd <= WIN && dd >= -WIN) ? 0.f : __expf(s[nf][c]);
                    s[nf][c] = e;
                    if (c < 2) lsum0 += e; else lsum1 += e;
                }
            }
        } else {
#pragma unroll
            for (int nf = 0; nf < 8; nf++)
#pragma unroll
                for (int c = 0; c < 4; c++) {
                    float e = __expf(s[nf][c]);
                    s[nf][c] = e;
                    if (c < 2) lsum0 += e; else lsum1 += e;
                }
        }

        // ---- O += P V (P single fp16, V split) ----
#pragma unroll
        for (int kf = 0; kf < 4; kf++) {
            uint32_t A[4];
            A[0] = pack_h2(s[2*kf][0],   s[2*kf][1]);
            A[1] = pack_h2(s[2*kf][2],   s[2*kf][3]);
            A[2] = pack_h2(s[2*kf+1][0], s[2*kf+1][1]);
            A[3] = pack_h2(s[2*kf+1][2], s[2*kf+1][3]);
            uint32_t va = sb + 1 * A_KV_TILE + vb_off + (uint32_t)(kf * 16 * A_PITCH);
#pragma unroll
            for (int np = 0; np < 4; np++) {
                uint32_t vh4[4], vl4[4];
                ldsm4t(vh4, va + np * 32);
                ldsm4t(vl4, va + np * 32 + A_KV_TILE);
                mma16816(o[2*np],   A, vh4[0], vh4[1]);
                mma16816(o[2*np],   A, vl4[0], vl4[1]);
                mma16816(o[2*np+1], A, vh4[2], vh4[3]);
                mma16816(o[2*np+1], A, vl4[2], vl4[3]);
            }
        }

        __syncthreads();
        if (ch + 2 < 32) { KV_LOAD(ch + 2, ch & 1); cp_commit(); }
    }

    // ---- reduce row sums across the quad, normalize, store ----
    lsum0 += __shfl_xor_sync(0xffffffffu, lsum0, 1);
    lsum0 += __shfl_xor_sync(0xffffffffu, lsum0, 2);
    lsum1 += __shfl_xor_sync(0xffffffffu, lsum1, 1);
    lsum1 += __shfl_xor_sync(0xffffffffu, lsum1, 2);
    float inv0 = 1.0f / lsum0;
    float inv1 = 1.0f / lsum1;

#pragma unroll
    for (int nf = 0; nf < 8; nf++) {
        int d = h * 64 + nf * 8 + 2 * (lane & 3);
        float2 v0 = make_float2(o[nf][0] * inv0, o[nf][1] * inv0);
        float2 v1 = make_float2(o[nf][2] * inv1, o[nf][3] * inv1);
        *(float2*)&out[((size_t)b * S_ + r0) * E_ + d] = v0;
        *(float2*)&out[((size_t)b * S_ + r1) * E_ + d] = v1;
    }
#undef KV_LOAD
}

// ---------------------------------------------------------------------------
extern "C" void kernel_launch(void* const* d_in, const int* in_sizes, int n_in,
                              void* d_out, int out_size)
{
    const float* X  = (const float*)d_in[0];
    const float* Wq = (const float*)d_in[1];
    const float* bq = (const float*)d_in[2];
    const float* Wk = (const float*)d_in[3];
    const float* bk = (const float*)d_in[4];
    const float* Wv = (const float*)d_in[5];
    const float* bv = (const float*)d_in[6];
    float* out = (float*)d_out;

    f16 *xh, *xl, *wq, *wk, *wvh, *wvl, *qh, *kh, *vh, *vl;
    cudaGetSymbolAddress((void**)&xh,  g_xh);
    cudaGetSymbolAddress((void**)&xl,  g_xl);
    cudaGetSymbolAddress((void**)&wq,  g_wq);
    cudaGetSymbolAddress((void**)&wk,  g_wk);
    cudaGetSymbolAddress((void**)&wvh, g_wvh);
    cudaGetSymbolAddress((void**)&wvl, g_wvl);
    cudaGetSymbolAddress((void**)&qh,  g_qh);
    cudaGetSymbolAddress((void**)&kh,  g_kh);
    cudaGetSymbolAddress((void**)&vh,  g_vh);
    cudaGetSymbolAddress((void**)&vl,  g_vl);

    cvt_pair  <<<(MS_*E_/4 + 255)/256, 256>>>(X,  xh, xl, MS_*E_/4);
    cvt_single<<<(E_*E_/4 + 255)/256, 256>>>(Wq, wq, E_*E_/4);
    cvt_single<<<(E_*E_/4 + 255)/256, 256>>>(Wk, wk, E_*E_/4);
    cvt_pair  <<<(E_*E_/4 + 255)/256, 256>>>(Wv, wvh, wvl, E_*E_/4);

    cudaFuncSetAttribute(proj_single,
                         cudaFuncAttributeMaxDynamicSharedMemorySize, P1_SMEM);
    cudaFuncSetAttribute(proj_split,
                         cudaFuncAttributeMaxDynamicSharedMemorySize, P3_SMEM);
    dim3 pgrid(E_ / 128, MS_ / 128);   // (8, 32)
    proj_single<<<pgrid, 256, P1_SMEM>>>(wq, bq, 0.125f, qh);
    proj_single<<<pgrid, 256, P1_SMEM>>>(wk, bk, 1.0f,   kh);
    proj_split <<<pgrid, 256, P3_SMEM>>>(wvh, wvl, bv, vh, vl);

    cudaFuncSetAttribute(attn_mma,
                         cudaFuncAttributeMaxDynamicSharedMemorySize, A_SMEM);
    dim3 agrid(S_ / 128, H_, B_);      // (16, 16, 2)
    attn_mma<<<agrid, 256, A_SMEM>>>(out);
}

// round 5
// speedup vs baseline: 6.8302x; 1.4919x over previous
#include <cuda_runtime.h>
#include <cuda_fp16.h>
#include <cstdint>

#define B_   2
#define S_   2048
#define E_   1024
#define H_   16
#define D_   64
#define WIN  3
#define MS_  (B_*S_)          // 4096 rows

typedef __half f16;

// ---------------------------------------------------------------------------
// Device-global scratch (allocation-free)
// ---------------------------------------------------------------------------
__device__ f16 g_x[MS_*E_];                         // X fp16
__device__ f16 g_wq[E_*E_], g_wk[E_*E_], g_wv[E_*E_];
__device__ f16 g_qh[B_*H_*S_*D_];                   // Q (prescaled 1/8)
__device__ f16 g_kh[B_*H_*S_*D_];
__device__ f16 g_vh[B_*H_*S_*D_];

// ---------------------------------------------------------------------------
// Helpers (plain sm_80-level PTX: cp.async / ldmatrix / mma.sync)
// ---------------------------------------------------------------------------
__device__ __forceinline__ uint32_t smem_u32(const void* p) {
    uint32_t a;
    asm("{ .reg .u64 t; cvta.to.shared.u64 t, %1; cvt.u32.u64 %0, t; }"
        : "=r"(a) : "l"(p));
    return a;
}
__device__ __forceinline__ void cp16(uint32_t dst, const void* src) {
    asm volatile("cp.async.cg.shared.global [%0], [%1], 16;"
                 :: "r"(dst), "l"(src) : "memory");
}
__device__ __forceinline__ void cp_commit() {
    asm volatile("cp.async.commit_group;" ::: "memory");
}
template <int N>
__device__ __forceinline__ void cp_wait() {
    asm volatile("cp.async.wait_group %0;" :: "n"(N) : "memory");
}
__device__ __forceinline__ void ldsm4(uint32_t* r, uint32_t addr) {
    asm volatile("ldmatrix.sync.aligned.m8n8.x4.shared.b16 {%0,%1,%2,%3}, [%4];"
                 : "=r"(r[0]), "=r"(r[1]), "=r"(r[2]), "=r"(r[3]) : "r"(addr));
}
__device__ __forceinline__ void ldsm4t(uint32_t* r, uint32_t addr) {
    asm volatile("ldmatrix.sync.aligned.m8n8.x4.trans.shared.b16 {%0,%1,%2,%3}, [%4];"
                 : "=r"(r[0]), "=r"(r[1]), "=r"(r[2]), "=r"(r[3]) : "r"(addr));
}
__device__ __forceinline__ void mma16816(float* c, const uint32_t* a,
                                         uint32_t b0, uint32_t b1) {
    asm volatile(
        "mma.sync.aligned.m16n8k16.row.col.f32.f16.f16.f32 "
        "{%0,%1,%2,%3}, {%4,%5,%6,%7}, {%8,%9}, {%0,%1,%2,%3};"
        : "+f"(c[0]), "+f"(c[1]), "+f"(c[2]), "+f"(c[3])
        : "r"(a[0]), "r"(a[1]), "r"(a[2]), "r"(a[3]), "r"(b0), "r"(b1));
}
__device__ __forceinline__ uint32_t pack_h2(float x, float y) {
    __half2 h = __floats2half2_rn(x, y);
    return *reinterpret_cast<uint32_t*>(&h);
}

// ---------------------------------------------------------------------------
// fp32 -> fp16 conversion
// ---------------------------------------------------------------------------
__global__ __launch_bounds__(256) void cvt_single(
    const float* __restrict__ src, f16* __restrict__ dst, int n4)
{
    int i = blockIdx.x * blockDim.x + threadIdx.x;
    if (i >= n4) return;
    float4 v = ((const float4*)src)[i];
    ((uint32_t*)dst)[i * 2 + 0] = pack_h2(v.x, v.y);
    ((uint32_t*)dst)[i * 2 + 1] = pack_h2(v.z, v.w);
}

// ---------------------------------------------------------------------------
// Fused projection GEMM (Q, K, V selected by blockIdx.z):
//   out[m][n] = (X[m,:] . W[n,:] + bias[n]) * scale -> fp16 [b,h,s,d]
// CTA 128x128, K-chunk 32, 8 warps (2m x 4n), warp tile 64x32, pitch 80B.
// smem: 2 stages x [A, B] = 40960 B -> 2 CTAs/SM.
// ---------------------------------------------------------------------------
#define P_PITCH 80
#define P_TILE  (128 * P_PITCH)        // 10240 B
#define P_STAGE (2 * P_TILE)
#define P_SMEM  (2 * P_STAGE)          // 40960

__global__ __launch_bounds__(256, 2) void proj_fused(
    const f16* __restrict__ Wq_, const float* __restrict__ bq_,
    const f16* __restrict__ Wk_, const float* __restrict__ bk_,
    const f16* __restrict__ Wv_, const float* __restrict__ bv_,
    f16* __restrict__ Dq_, f16* __restrict__ Dk_, f16* __restrict__ Dv_)
{
    const int z = blockIdx.z;
    const f16*   W    = (z == 0) ? Wq_ : (z == 1) ? Wk_ : Wv_;
    const float* bias = (z == 0) ? bq_ : (z == 1) ? bk_ : bv_;
    f16*         Dst  = (z == 0) ? Dq_ : (z == 1) ? Dk_ : Dv_;
    const float scale = (z == 0) ? 0.125f : 1.0f;

    extern __shared__ char sm[];
    const uint32_t smb = smem_u32(sm);
    const int tid  = threadIdx.x;
    const int lane = tid & 31;
    const int wid  = tid >> 5;
    const int wm   = wid >> 2;
    const int wn   = wid & 3;
    const int m0   = blockIdx.y * 128;
    const int n0   = blockIdx.x * 128;

    const int lr = tid >> 1;
    const int lh = tid & 1;
    const f16* gx = g_x + (size_t)(m0 + lr) * E_ + lh * 16;
    const f16* gw = W   + (size_t)(n0 + lr) * E_ + lh * 16;
    const uint32_t soff = (uint32_t)(lr * P_PITCH + lh * 32);

#define P_LOAD(ch, stg) do {                                                  \
    uint32_t sb = smb + (stg) * P_STAGE + soff;                               \
    int k0 = (ch) * 32;                                                       \
    cp16(sb +  0, gx + k0);  cp16(sb + 16, gx + k0 + 8);                      \
    cp16(sb + P_TILE +  0, gw + k0);  cp16(sb + P_TILE + 16, gw + k0 + 8);    \
} while (0)

    float acc[4][4][4];
#pragma unroll
    for (int i = 0; i < 4; i++)
#pragma unroll
        for (int j = 0; j < 4; j++)
#pragma unroll
            for (int c = 0; c < 4; c++) acc[i][j][c] = 0.f;

    P_LOAD(0, 0); cp_commit();
    P_LOAD(1, 1); cp_commit();

    const uint32_t a_off = (uint32_t)((wm * 64 + (lane & 15)) * P_PITCH + (lane >> 4) * 16);
    const uint32_t b_off = (uint32_t)((wn * 32 + (lane & 7)) * P_PITCH + (lane >> 3) * 16);

    for (int ch = 0; ch < 32; ch++) {
        if (ch >= 30) cp_wait<0>(); else cp_wait<1>();
        __syncthreads();
        const uint32_t sb = smb + (ch & 1) * P_STAGE;

        uint32_t bh[4][4];
#pragma unroll
        for (int nf = 0; nf < 4; nf++)
            ldsm4(bh[nf], sb + P_TILE + b_off + (uint32_t)(nf * 8 * P_PITCH));

#pragma unroll
        for (int kf = 0; kf < 2; kf++) {
            uint32_t ah[4][4];
#pragma unroll
            for (int mf = 0; mf < 4; mf++)
                ldsm4(ah[mf], sb + a_off + (uint32_t)(mf * 16 * P_PITCH + kf * 32));
#pragma unroll
            for (int mf = 0; mf < 4; mf++)
#pragma unroll
                for (int nf = 0; nf < 4; nf++)
                    mma16816(acc[mf][nf], ah[mf], bh[nf][kf*2], bh[nf][kf*2+1]);
        }
        __syncthreads();
        if (ch + 2 < 32) { P_LOAD(ch + 2, ch & 1); cp_commit(); }
    }

#pragma unroll
    for (int mf = 0; mf < 4; mf++) {
        int r0 = m0 + wm * 64 + mf * 16 + (lane >> 2);
        int r1 = r0 + 8;
        int b0i = r0 >> 11, s0i = r0 & (S_ - 1);
        int b1i = r1 >> 11, s1i = r1 & (S_ - 1);
#pragma unroll
        for (int nf = 0; nf < 4; nf++) {
            int n = n0 + wn * 32 + nf * 8 + 2 * (lane & 3);
            float2 bv = *(const float2*)&bias[n];
            uint32_t p0 = pack_h2((acc[mf][nf][0] + bv.x) * scale,
                                  (acc[mf][nf][1] + bv.y) * scale);
            uint32_t p1 = pack_h2((acc[mf][nf][2] + bv.x) * scale,
                                  (acc[mf][nf][3] + bv.y) * scale);
            int h = n >> 6, d = n & 63;
            size_t i0 = (((size_t)b0i * H_ + h) * S_ + s0i) * D_ + d;
            size_t i1 = (((size_t)b1i * H_ + h) * S_ + s1i) * D_ + d;
            *(uint32_t*)(Dst + i0) = p0;
            *(uint32_t*)(Dst + i1) = p1;
        }
    }
#undef P_LOAD
}

// ---------------------------------------------------------------------------
// Attention: all-fp16 operands, fp32 accum. Inverted-band mask, no online max.
// CTA: 128 q x (b,h); 8 warps x 16 q-rows; KV tile 64, double-buffered.
// smem: 2 stages x [Kh, Vh] x 9216 = 36864 -> 2 CTAs/SM.
// ---------------------------------------------------------------------------
#define A_PITCH   144
#define A_KV_TILE (64 * A_PITCH)       // 9216
#define A_STAGE   (2 * A_KV_TILE)      // 18432
#define A_SMEM    (2 * A_STAGE)        // 36864

__global__ __launch_bounds__(256, 2) void attn_mma(float* __restrict__ out)
{
    extern __shared__ char sm[];
    const uint32_t smb = smem_u32(sm);
    const int tid  = threadIdx.x;
    const int lane = tid & 31;
    const int w    = tid >> 5;
    const int q0   = blockIdx.x * 128;
    const int h    = blockIdx.y;
    const int b    = blockIdx.z;

    const size_t base = ((size_t)b * H_ + h) * S_ * D_;
    const f16* Qh = g_qh + base;
    const f16* Kh = g_kh + base;
    const f16* Vh = g_vh + base;

    // ---- stage Q, extract fragments, release smem ----
    {
        int r = tid >> 1;
        int c = (tid & 1) * 4;
        const f16* q = Qh + (size_t)(q0 + r) * D_ + c * 8;
        uint32_t sh = smb + (uint32_t)(r * A_PITCH + c * 16);
#pragma unroll
        for (int i = 0; i < 4; i++) cp16(sh + i * 16, q + i * 8);
        cp_commit();
        cp_wait<0>();
        __syncthreads();
    }
    uint32_t qf[4][4];
    {
        uint32_t qa = smb + (uint32_t)((w * 16 + (lane & 15)) * A_PITCH + (lane >> 4) * 16);
#pragma unroll
        for (int kf = 0; kf < 4; kf++) ldsm4(qf[kf], qa + kf * 32);
    }
    __syncthreads();

    const int lr = tid >> 2;
    const int lc = (tid & 3) * 2;
    const uint32_t kvoff = (uint32_t)(lr * A_PITCH + lc * 16);

#define KV_LOAD(ch, stg) do {                                                  \
    size_t g = (size_t)((ch) * 64 + lr) * D_ + lc * 8;                         \
    uint32_t sb = smb + (stg) * A_STAGE + kvoff;                               \
    cp16(sb,              Kh + g); cp16(sb + 16,             Kh + g + 8);      \
    cp16(sb + A_KV_TILE,  Vh + g); cp16(sb + A_KV_TILE + 16, Vh + g + 8);      \
} while (0)

    float o[8][4];
#pragma unroll
    for (int i = 0; i < 8; i++)
#pragma unroll
        for (int c = 0; c < 4; c++) o[i][c] = 0.f;
    float lsum0 = 0.f, lsum1 = 0.f;

    KV_LOAD(0, 0); cp_commit();
    KV_LOAD(1, 1); cp_commit();

    const int r0 = q0 + w * 16 + (lane >> 2);
    const int r1 = r0 + 8;
    const uint32_t kb_off = (uint32_t)((lane & 7) * A_PITCH + (lane >> 3) * 16);
    const uint32_t vb_off = (uint32_t)((lane & 15) * A_PITCH + (lane >> 4) * 16);

    for (int ch = 0; ch < 32; ch++) {
        if (ch >= 30) cp_wait<0>(); else cp_wait<1>();
        __syncthreads();

        const uint32_t sb = smb + (ch & 1) * A_STAGE;
        const int kt = ch * 64;

        // ---- S = Q K^T ----
        float s[8][4];
#pragma unroll
        for (int i = 0; i < 8; i++)
#pragma unroll
            for (int c = 0; c < 4; c++) s[i][c] = 0.f;

#pragma unroll
        for (int nf = 0; nf < 8; nf++) {
            uint32_t ka = sb + kb_off + (uint32_t)(nf * 8 * A_PITCH);
#pragma unroll
            for (int p = 0; p < 2; p++) {
                uint32_t k4[4];
                ldsm4(k4, ka + p * 64);
                mma16816(s[nf], qf[2*p],   k4[0], k4[1]);
                mma16816(s[nf], qf[2*p+1], k4[2], k4[3]);
            }
        }

        // ---- mask + exp + row sums ----
        bool need_mask = (kt + 63 >= q0 - WIN) && (kt <= q0 + 127 + WIN);
        if (need_mask) {
#pragma unroll
            for (int nf = 0; nf < 8; nf++) {
                int kcol = kt + nf * 8 + 2 * (lane & 3);
#pragma unroll
                for (int c = 0; c < 4; c++) {
                    int qg = (c < 2) ? r0 : r1;
                    int dd = qg - (kcol + (c & 1));
                    float e = (dd <= WIN && dd >= -WIN) ? 0.f : __expf(s[nf][c]);
                    s[nf][c] = e;
                    if (c < 2) lsum0 += e; else lsum1 += e;
                }
            }
        } else {
#pragma unroll
            for (int nf = 0; nf < 8; nf++)
#pragma unroll
                for (int c = 0; c < 4; c++) {
                    float e = __expf(s[nf][c]);
                    s[nf][c] = e;
                    if (c < 2) lsum0 += e; else lsum1 += e;
                }
        }

        // ---- O += P V ----
#pragma unroll
        for (int kf = 0; kf < 4; kf++) {
            uint32_t A[4];
            A[0] = pack_h2(s[2*kf][0],   s[2*kf][1]);
            A[1] = pack_h2(s[2*kf][2],   s[2*kf][3]);
            A[2] = pack_h2(s[2*kf+1][0], s[2*kf+1][1]);
            A[3] = pack_h2(s[2*kf+1][2], s[2*kf+1][3]);
            uint32_t va = sb + A_KV_TILE + vb_off + (uint32_t)(kf * 16 * A_PITCH);
#pragma unroll
            for (int np = 0; np < 4; np++) {
                uint32_t v4[4];
                ldsm4t(v4, va + np * 32);
                mma16816(o[2*np],   A, v4[0], v4[1]);
                mma16816(o[2*np+1], A, v4[2], v4[3]);
            }
        }

        __syncthreads();
        if (ch + 2 < 32) { KV_LOAD(ch + 2, ch & 1); cp_commit(); }
    }

    // ---- reduce row sums across the quad, normalize, store ----
    lsum0 += __shfl_xor_sync(0xffffffffu, lsum0, 1);
    lsum0 += __shfl_xor_sync(0xffffffffu, lsum0, 2);
    lsum1 += __shfl_xor_sync(0xffffffffu, lsum1, 1);
    lsum1 += __shfl_xor_sync(0xffffffffu, lsum1, 2);
    float inv0 = 1.0f / lsum0;
    float inv1 = 1.0f / lsum1;

#pragma unroll
    for (int nf = 0; nf < 8; nf++) {
        int d = h * 64 + nf * 8 + 2 * (lane & 3);
        float2 v0 = make_float2(o[nf][0] * inv0, o[nf][1] * inv0);
        float2 v1 = make_float2(o[nf][2] * inv1, o[nf][3] * inv1);
        *(float2*)&out[((size_t)b * S_ + r0) * E_ + d] = v0;
        *(float2*)&out[((size_t)b * S_ + r1) * E_ + d] = v1;
    }
#undef KV_LOAD
}

// ---------------------------------------------------------------------------
extern "C" void kernel_launch(void* const* d_in, const int* in_sizes, int n_in,
                              void* d_out, int out_size)
{
    const float* X  = (const float*)d_in[0];
    const float* Wq = (const float*)d_in[1];
    const float* bq = (const float*)d_in[2];
    const float* Wk = (const float*)d_in[3];
    const float* bk = (const float*)d_in[4];
    const float* Wv = (const float*)d_in[5];
    const float* bv = (const float*)d_in[6];
    float* out = (float*)d_out;

    f16 *x, *wq, *wk, *wv, *qh, *kh, *vh;
    cudaGetSymbolAddress((void**)&x,  g_x);
    cudaGetSymbolAddress((void**)&wq, g_wq);
    cudaGetSymbolAddress((void**)&wk, g_wk);
    cudaGetSymbolAddress((void**)&wv, g_wv);
    cudaGetSymbolAddress((void**)&qh, g_qh);
    cudaGetSymbolAddress((void**)&kh, g_kh);
    cudaGetSymbolAddress((void**)&vh, g_vh);

    cvt_single<<<(MS_*E_/4 + 255)/256, 256>>>(X,  x,  MS_*E_/4);
    cvt_single<<<(E_*E_/4 + 255)/256, 256>>>(Wq, wq, E_*E_/4);
    cvt_single<<<(E_*E_/4 + 255)/256, 256>>>(Wk, wk, E_*E_/4);
    cvt_single<<<(E_*E_/4 + 255)/256, 256>>>(Wv, wv, E_*E_/4);

    cudaFuncSetAttribute(proj_fused,
                         cudaFuncAttributeMaxDynamicSharedMemorySize, P_SMEM);
    dim3 pgrid(E_ / 128, MS_ / 128, 3);   // (8, 32, 3)
    proj_fused<<<pgrid, 256, P_SMEM>>>(wq, bq, wk, bk, wv, bv, qh, kh, vh);

    cudaFuncSetAttribute(attn_mma,
                         cudaFuncAttributeMaxDynamicSharedMemorySize, A_SMEM);
    dim3 agrid(S_ / 128, H_, B_);      // (16, 16, 2)
    attn_mma<<<agrid, 256, A_SMEM>>>(out);
}